// round 6
// baseline (speedup 1.0000x reference)
#include <cuda_runtime.h>

// TensorReduce_88536455839845 — NeRF over-compositing, R6.
// Persistent warps + rotated 2-buffer software pipeline: each warp processes
// ~27 rays, prefetching ray i+1's 12 global loads before computing ray i.
// Removes the 11 wave transitions / CTA ramp-drain bubbles that capped R3/R5
// at DRAM=80%.
//
// rgba:     [65536, 192, 4] f32  (d_in[0])
// distance: [65536, 192]    f32  (d_in[1])
// out:      [65536, 3]      f32

#define NR_RAYS    65536
#define NR_SAMPLES 192
#define NR_CHUNKS  6

#define EPS_DIST   1e-5f
#define EPS_ALPHA  1e-8f
#define FAR_DELTA  1e4f

__device__ __forceinline__ float fast_sigmoid(float x) {
    return __fdividef(1.0f, 1.0f + __expf(-x));
}

struct RayBuf {
    float4 v[NR_CHUNKS];
    float  d[NR_CHUNKS];
};

__device__ __forceinline__ void load_ray(
    const float4* __restrict__ rgba, const float* __restrict__ dist,
    int ray, int lane, RayBuf& b)
{
    const float4* rr = rgba + (size_t)ray * NR_SAMPLES;
    const float*  rd = dist + (size_t)ray * NR_SAMPLES;
    #pragma unroll
    for (int k = 0; k < NR_CHUNKS; ++k) {
        int s = (k << 5) + lane;
        b.v[k] = __ldcs(&rr[s]);
        b.d[k] = __ldcs(&rd[s]);
    }
}

__device__ __forceinline__ void compute_ray(
    const RayBuf& b, int ray, int lane, float* __restrict__ out)
{
    const unsigned FULL = 0xffffffffu;

    float alpha[NR_CHUNKS];
    float incl[NR_CHUNKS];
    #pragma unroll
    for (int k = 0; k < NR_CHUNKS; ++k) {
        // d[s+1]: neighbor lane; lane 31 takes next chunk's lane 0.
        float nxt = (k < NR_CHUNKS - 1) ? __shfl_sync(FULL, b.d[k + 1], 0) : b.d[k];
        float d1  = __shfl_down_sync(FULL, b.d[k], 1);
        if (lane == 31) d1 = nxt;

        bool  last  = (k == NR_CHUNKS - 1) && (lane == 31);
        float delta = last ? FAR_DELTA : fabsf(d1 - b.d[k]);

        float density = (b.d[k] < EPS_DIST) ? 0.0f : fmaxf(b.v[k].w, 0.0f);

        float a  = 1.0f - __expf(-delta * density);
        alpha[k] = a;
        incl[k]  = 1.0f - a + EPS_ALPHA;       // strictly > 0
    }

    // 6 independent inclusive product scans, interleaved for ILP.
    #pragma unroll
    for (int off = 1; off < 32; off <<= 1) {
        #pragma unroll
        for (int k = 0; k < NR_CHUNKS; ++k) {
            float t = __shfl_up_sync(FULL, incl[k], off);
            if (lane >= off) incl[k] *= t;
        }
    }

    float excl[NR_CHUNKS], tot[NR_CHUNKS];
    #pragma unroll
    for (int k = 0; k < NR_CHUNKS; ++k) {
        float e = __shfl_up_sync(FULL, incl[k], 1);
        excl[k] = (lane == 0) ? 1.0f : e;
        tot[k]  = __shfl_sync(FULL, incl[k], 31);
    }

    float carry = 1.0f;
    float r_acc = 0.0f, g_acc = 0.0f, b_acc = 0.0f;
    #pragma unroll
    for (int k = 0; k < NR_CHUNKS; ++k) {
        float w = alpha[k] * carry * excl[k];
        r_acc = fmaf(w, fast_sigmoid(b.v[k].x), r_acc);
        g_acc = fmaf(w, fast_sigmoid(b.v[k].y), g_acc);
        b_acc = fmaf(w, fast_sigmoid(b.v[k].z), b_acc);
        carry *= tot[k];
    }

    #pragma unroll
    for (int off = 16; off > 0; off >>= 1) {
        r_acc += __shfl_down_sync(FULL, r_acc, off);
        g_acc += __shfl_down_sync(FULL, g_acc, off);
        b_acc += __shfl_down_sync(FULL, b_acc, off);
    }

    if (lane == 0) {
        float* o = out + (size_t)ray * 3;
        o[0] = r_acc;
        o[1] = g_acc;
        o[2] = b_acc;
    }
}

__global__ __launch_bounds__(256, 2) void composite_kernel(
    const float4* __restrict__ rgba,
    const float*  __restrict__ dist,
    float*        __restrict__ out)
{
    int gwarp  = (blockIdx.x * blockDim.x + threadIdx.x) >> 5;
    int lane   = threadIdx.x & 31;
    int stride = (gridDim.x * blockDim.x) >> 5;   // total warps

    int ray = gwarp;
    if (ray >= NR_RAYS) return;

    RayBuf A, B;
    load_ray(rgba, dist, ray, lane, A);

    // Rotated 2-buffer pipeline: prefetch next ray's loads before computing
    // the current ray. All branch conditions are warp-uniform.
    while (true) {
        int n1 = ray + stride;
        if (n1 < NR_RAYS) load_ray(rgba, dist, n1, lane, B);
        compute_ray(A, ray, lane, out);
        if (n1 >= NR_RAYS) break;

        int n2 = n1 + stride;
        if (n2 < NR_RAYS) load_ray(rgba, dist, n2, lane, A);
        compute_ray(B, n1, lane, out);
        if (n2 >= NR_RAYS) break;

        ray = n2;
    }
}

extern "C" void kernel_launch(void* const* d_in, const int* in_sizes, int n_in,
                              void* d_out, int out_size) {
    const float4* rgba = (const float4*)d_in[0];
    const float*  dist = (const float*)d_in[1];
    float* out = (float*)d_out;

    int dev = 0, sms = 148;
    cudaGetDevice(&dev);
    cudaDeviceGetAttribute(&sms, cudaDevAttrMultiProcessorCount, dev);

    dim3 block(256);
    dim3 grid(sms * 2);   // persistent: exactly 2 CTAs per SM
    composite_kernel<<<grid, block>>>(rgba, dist, out);
}

// round 7
// speedup vs baseline: 1.0600x; 1.0600x over previous
#include <cuda_runtime.h>

// TensorReduce_88536455839845 — NeRF over-compositing, R7.
// = R3 (best: 41.0us, DRAM 80%) + MUFU.TANH sigmoid (halves MUFU ops/ray,
// shortening the per-warp compute tail that stalls its memory stream).
//
// rgba:     [65536, 192, 4] f32  (d_in[0])
// distance: [65536, 192]    f32  (d_in[1])
// out:      [65536, 3]      f32

#define NR_RAYS    65536
#define NR_SAMPLES 192
#define NR_CHUNKS  6

#define EPS_DIST   1e-5f
#define EPS_ALPHA  1e-8f
#define FAR_DELTA  1e4f

// sigmoid(x) = 0.5*tanh(x/2) + 0.5 ; __tanhf -> single MUFU.TANH on sm_103a
__device__ __forceinline__ float fast_sigmoid(float x) {
    return fmaf(0.5f, __tanhf(0.5f * x), 0.5f);
}

__global__ __launch_bounds__(256, 4) void composite_kernel(
    const float4* __restrict__ rgba,     // [N, S] float4
    const float*  __restrict__ dist,     // [N, S]
    float*        __restrict__ out)      // [N, 3]
{
    const unsigned FULL = 0xffffffffu;
    int gwarp = (blockIdx.x * blockDim.x + threadIdx.x) >> 5;
    int lane  = threadIdx.x & 31;
    if (gwarp >= NR_RAYS) return;

    const float4* ray_rgba = rgba + (size_t)gwarp * NR_SAMPLES;
    const float*  ray_dist = dist + (size_t)gwarp * NR_SAMPLES;

    // ---- Phase 1: ALL global loads up front (streaming, evict-first) ----
    float4 v[NR_CHUNKS];
    float  d0[NR_CHUNKS];
    #pragma unroll
    for (int k = 0; k < NR_CHUNKS; ++k) {
        int s = (k << 5) + lane;
        v[k]  = __ldcs(&ray_rgba[s]);
        d0[k] = __ldcs(&ray_dist[s]);
    }

    // ---- Phase 2: alpha / (1-alpha+eps) per chunk ----
    float alpha[NR_CHUNKS];
    float incl[NR_CHUNKS];
    #pragma unroll
    for (int k = 0; k < NR_CHUNKS; ++k) {
        // d[s+1]: neighbor lane's value; lane 31 takes next chunk's lane 0.
        float nxt = (k < NR_CHUNKS - 1) ? __shfl_sync(FULL, d0[k + 1], 0) : d0[k];
        float d1  = __shfl_down_sync(FULL, d0[k], 1);
        if (lane == 31) d1 = nxt;

        bool  last  = (k == NR_CHUNKS - 1) && (lane == 31);
        float delta = last ? FAR_DELTA : fabsf(d1 - d0[k]);

        float density = (d0[k] < EPS_DIST) ? 0.0f : fmaxf(v[k].w, 0.0f);

        float a  = 1.0f - __expf(-delta * density);
        alpha[k] = a;
        incl[k]  = 1.0f - a + EPS_ALPHA;        // strictly > 0
    }

    // ---- Phase 3: 6 independent inclusive product scans, interleaved ----
    #pragma unroll
    for (int off = 1; off < 32; off <<= 1) {
        #pragma unroll
        for (int k = 0; k < NR_CHUNKS; ++k) {
            float t = __shfl_up_sync(FULL, incl[k], off);
            if (lane >= off) incl[k] *= t;
        }
    }

    // Exclusive value + per-chunk totals (all independent)
    float excl[NR_CHUNKS], tot[NR_CHUNKS];
    #pragma unroll
    for (int k = 0; k < NR_CHUNKS; ++k) {
        float e = __shfl_up_sync(FULL, incl[k], 1);
        excl[k] = (lane == 0) ? 1.0f : e;
        tot[k]  = __shfl_sync(FULL, incl[k], 31);
    }

    // ---- Phase 4: carry chain + weighted accumulate ----
    float carry = 1.0f;
    float r_acc = 0.0f, g_acc = 0.0f, b_acc = 0.0f;
    #pragma unroll
    for (int k = 0; k < NR_CHUNKS; ++k) {
        float w = alpha[k] * carry * excl[k];
        r_acc = fmaf(w, fast_sigmoid(v[k].x), r_acc);
        g_acc = fmaf(w, fast_sigmoid(v[k].y), g_acc);
        b_acc = fmaf(w, fast_sigmoid(v[k].z), b_acc);
        carry *= tot[k];
    }

    // ---- Warp tree-reduce the 3 accumulators ----
    #pragma unroll
    for (int off = 16; off > 0; off >>= 1) {
        r_acc += __shfl_down_sync(FULL, r_acc, off);
        g_acc += __shfl_down_sync(FULL, g_acc, off);
        b_acc += __shfl_down_sync(FULL, b_acc, off);
    }

    if (lane == 0) {
        float* o = out + (size_t)gwarp * 3;
        o[0] = r_acc;
        o[1] = g_acc;
        o[2] = b_acc;
    }
}

extern "C" void kernel_launch(void* const* d_in, const int* in_sizes, int n_in,
                              void* d_out, int out_size) {
    const float4* rgba = (const float4*)d_in[0];
    const float*  dist = (const float*)d_in[1];
    float* out = (float*)d_out;

    dim3 block(256);
    dim3 grid((NR_RAYS * 32) / 256);   // 1 warp per ray
    composite_kernel<<<grid, block>>>(rgba, dist, out);
}